// round 1
// baseline (speedup 1.0000x reference)
#include <cuda_runtime.h>
#include <math.h>

#define BATCH   65536
#define UNITS   256
#define DIN     256
#define KTOT    512           // DIN + UNITS
#define BM      64
#define BK      16
#define AS_STRIDE 66          // 64 + 2 pad (keeps 8B alignment for paired LDS.64)
#define BS_STRIDE 520         // 512 duplicated + 8 pad

typedef unsigned long long u64;

__device__ __forceinline__ u64 fma_f32x2(u64 a, u64 b, u64 c) {
    u64 d;
    asm("fma.rn.f32x2 %0, %1, %2, %3;" : "=l"(d) : "l"(a), "l"(b), "l"(c));
    return d;
}

__device__ __forceinline__ float lo32(u64 v) { return __uint_as_float((unsigned)(v & 0xffffffffull)); }
__device__ __forceinline__ float hi32(u64 v) { return __uint_as_float((unsigned)(v >> 32)); }

__global__ __launch_bounds__(256, 2)
void jfc_kernel(const float* __restrict__ inputs,
                const float* __restrict__ prev_h,
                const float* __restrict__ prev_G,
                const float* __restrict__ prev_phase,
                const float* __restrict__ w_in,
                const float* __restrict__ w_rec,
                const float* __restrict__ bias,
                float* __restrict__ out_h,
                float* __restrict__ out_G,
                float* __restrict__ out_phase)
{
    __shared__ __align__(16) float As[BK][AS_STRIDE];
    __shared__ __align__(16) float Bs[BK][BS_STRIDE];

    const int tid = threadIdx.x;
    const int tx  = tid & 31;      // lane -> column group
    const int ty  = tid >> 5;      // warp -> 8 contiguous rows (ty*8 .. ty*8+7)
    const int rowBase = blockIdx.x * BM;

    // Packed accumulators: acc[i2][j] holds rows (ty*8+2*i2, ty*8+2*i2+1), col tx+32*j
    u64 acc[4][8];
    #pragma unroll
    for (int i = 0; i < 4; i++)
        #pragma unroll
        for (int j = 0; j < 8; j++) acc[i][j] = 0ull;

    // A-tile load mapping: thread -> (row a_r, 4 consecutive k at a_k)
    const int a_r = tid >> 2;          // 0..63
    const int a_k = (tid & 3) * 4;     // 0,4,8,12
    // B-tile load mapping: thread -> (row b_k, lanes-of-16 column b_u0)
    const int b_k  = tid >> 4;         // 0..15
    const int b_u0 = tid & 15;         // 0..15

    for (int k0 = 0; k0 < KTOT; k0 += BK) {
        // ---- load A tile (transposed into SMEM) ----
        // A = [inputs | prev_h] row-major, K chunks never straddle (256 % 16 == 0)
        const float* asrc = (k0 < DIN)
            ? (inputs + (size_t)(rowBase + a_r) * DIN + k0 + a_k)
            : (prev_h + (size_t)(rowBase + a_r) * UNITS + (k0 - DIN) + a_k);
        float4 av = *(const float4*)asrc;
        As[a_k + 0][a_r] = av.x;
        As[a_k + 1][a_r] = av.y;
        As[a_k + 2][a_r] = av.z;
        As[a_k + 3][a_r] = av.w;

        // ---- load B tile, value-duplicated for f32x2 broadcast via LDS.64 ----
        {
            const int kg = k0 + b_k;
            const float* wsrc = (kg < DIN) ? (w_in + (size_t)kg * UNITS)
                                           : (w_rec + (size_t)(kg - DIN) * UNITS);
            #pragma unroll
            for (int s = 0; s < 16; s++) {
                int u = b_u0 + 16 * s;
                float v = wsrc[u];
                *(float2*)&Bs[b_k][2 * u] = make_float2(v, v);
            }
        }
        __syncthreads();

        // ---- compute: 16 k-steps, 32 FFMA2 each ----
        #pragma unroll
        for (int kk = 0; kk < BK; kk++) {
            u64 a2[4], b2[8];
            #pragma unroll
            for (int i = 0; i < 4; i++)
                a2[i] = *(const u64*)&As[kk][ty * 8 + 2 * i];   // {row 2i, row 2i+1} broadcast
            #pragma unroll
            for (int j = 0; j < 8; j++)
                b2[j] = *(const u64*)&Bs[kk][2 * (tx + 32 * j)]; // {w, w}
            #pragma unroll
            for (int i = 0; i < 4; i++)
                #pragma unroll
                for (int j = 0; j < 8; j++)
                    acc[i][j] = fma_f32x2(a2[i], b2[j], acc[i][j]);
        }
        __syncthreads();
    }

    // ---------------- fused epilogue ----------------
    const float inv_units = 1.0f / (float)UNITS;
    const float dphase = 0.2513274122871834f;   // 2*pi/25

    float biasv[8];
    #pragma unroll
    for (int j = 0; j < 8; j++) biasv[j] = bias[tx + 32 * j];

    #pragma unroll
    for (int i = 0; i < 8; i++) {
        const int r = rowBase + ty * 8 + i;
        const size_t rowOff = (size_t)r * UNITS;

        float zpre[8], nG[8], ph[8];
        float sG = 0.f, sG2 = 0.f, sR = 0.f;
        #pragma unroll
        for (int j = 0; j < 8; j++) {
            const int c = tx + 32 * j;
            u64 v = acc[i >> 1][j];
            zpre[j] = (i & 1) ? hi32(v) : lo32(v);
            float raw = prev_h[rowOff + (c ^ 128)];   // half-swap == XOR 128
            float pg  = prev_G[rowOff + c];
            ph[j]     = prev_h[rowOff + c];
            float g   = 0.9f * pg + 0.1f * raw;
            nG[j] = g;
            sG  += g;
            sG2 += g * g;
            sR  += raw;
        }
        // warp reduction: all 32 lanes of this warp together hold the full row
        #pragma unroll
        for (int off = 16; off; off >>= 1) {
            sG  += __shfl_xor_sync(0xffffffffu, sG,  off);
            sG2 += __shfl_xor_sync(0xffffffffu, sG2, off);
            sR  += __shfl_xor_sync(0xffffffffu, sR,  off);
        }
        float mean  = sG * inv_units;
        float var   = fmaxf(sG2 * inv_units - mean * mean, 0.0f);
        float invd  = 1.0f / (sqrtf(var) + 1e-6f);
        float nphase = prev_phase[r] + dphase;
        float osc = sinf(nphase);
        float combined = osc + 0.05f * (sR * inv_units - 0.1f);
        float cf = 0.5f * combined;
        if (tx == 0) out_phase[r] = nphase;

        #pragma unroll
        for (int j = 0; j < 8; j++) {
            const int c = tx + 32 * j;
            float gn    = (nG[j] - mean) * invd;
            float field = 1.0f + cf * tanhf(gn);
            float z     = (zpre[j] + biasv[j]) * field;
            float e     = (z > 0.0f) ? z : expm1f(z);
            float h     = 0.9f * ph[j] + 0.1f * e;
            h = fminf(fmaxf(h, -20.0f), 20.0f);
            out_h[rowOff + c] = h;
            out_G[rowOff + c] = nG[j];
        }
    }
}

extern "C" void kernel_launch(void* const* d_in, const int* in_sizes, int n_in,
                              void* d_out, int out_size) {
    const float* inputs     = (const float*)d_in[0];
    const float* prev_h     = (const float*)d_in[1];
    const float* prev_G     = (const float*)d_in[2];
    const float* prev_phase = (const float*)d_in[3];
    const float* w_in       = (const float*)d_in[4];
    const float* w_rec      = (const float*)d_in[5];
    const float* bias       = (const float*)d_in[6];

    float* out   = (float*)d_out;
    float* out_h = out;                                    // [BATCH, UNITS]
    float* out_G = out + (size_t)BATCH * UNITS;            // [BATCH, UNITS]
    float* out_p = out + 2 * (size_t)BATCH * UNITS;        // [BATCH, 1]

    dim3 grid(BATCH / BM);
    dim3 block(256);
    jfc_kernel<<<grid, block>>>(inputs, prev_h, prev_G, prev_phase,
                                w_in, w_rec, bias, out_h, out_G, out_p);
}

// round 4
// speedup vs baseline: 2.1913x; 2.1913x over previous
#include <cuda_runtime.h>
#include <math.h>
#include <stdint.h>

#define BATCH 65536
#define UNITS 256
#define KTOT  512
#define TILE_M 128
#define BK 32
#define NSTAGE 16
#define NBLK (BATCH/TILE_M)

#define ASTRIDE 36                              // words per A row (32 + 4 pad, 144B)
#define ABUF_BYTES (TILE_M*ASTRIDE*4)           // 18432
#define BBUF_BYTES (BK*UNITS*4)                 // 32768
#define STATS_OFF  (2*ABUF_BYTES + 2*BBUF_BYTES)  // 102400
#define SMEM_BYTES (STATS_OFF + TILE_M*16)        // 104448

// Pre-baked weights: [q=0..63][n=0..255][p=0..3] float2 pairs,
// pair = { tf32(W[8q+p][n]), tf32(W[8q+p+4][n]) }   (mma b0/b1 = k=t4, k=t4+4)
__device__ __align__(16) float2 g_Bt[64*256*4];

// ---------------- helpers ----------------
__device__ __forceinline__ uint32_t smaddr(const void* p){
    uint32_t a;
    asm("{ .reg .u64 t; cvta.to.shared.u64 t, %1; cvt.u32.u64 %0, t; }" : "=r"(a) : "l"(p));
    return a;
}
__device__ __forceinline__ uint32_t cvt_tf32(float v){
    uint32_t t; asm("cvt.rna.tf32.f32 %0, %1;" : "=r"(t) : "f"(v)); return t;
}
__device__ __forceinline__ void cp16(uint32_t d, const void* s){
    asm volatile("cp.async.cg.shared.global [%0], [%1], 16;" :: "r"(d), "l"(s));
}
__device__ __forceinline__ uint2 lds64(uint32_t a){
    uint2 v;
    asm volatile("ld.shared.v2.b32 {%0,%1}, [%2];" : "=r"(v.x), "=r"(v.y) : "r"(a));
    return v;
}
__device__ __forceinline__ void sts64(uint32_t a, uint32_t v0, uint32_t v1){
    asm volatile("st.shared.v2.b32 [%0], {%1,%2};" :: "r"(a), "r"(v0), "r"(v1));
}
// d = {c0,c1,c2,c3}; a-regs in spec order a0=(g,t4) a1=(g+8,t4) a2=(g,t4+4) a3=(g+8,t4+4)
__device__ __forceinline__ void mma_tf32(float* d, uint2 rg, uint2 rg8, uint2 b){
    asm("mma.sync.aligned.m16n8k8.row.col.f32.tf32.tf32.f32 "
        "{%0,%1,%2,%3}, {%4,%5,%6,%7}, {%8,%9}, {%0,%1,%2,%3};"
        : "+f"(d[0]), "+f"(d[1]), "+f"(d[2]), "+f"(d[3])
        : "r"(rg.x), "r"(rg8.x), "r"(rg.y), "r"(rg8.y), "r"(b.x), "r"(b.y));
}

// ---------------- prep: tf32-convert + (k, k+4)-pair weights ----------------
__global__ void prep_B(const float* __restrict__ w_in, const float* __restrict__ w_rec){
    int t = blockIdx.x * 256 + threadIdx.x;        // 0..65535
    int p = t & 3, n = (t >> 2) & 255, q = t >> 10;
    int k0 = 8*q + p;
    int k1 = k0 + 4;
    const float* W0 = (k0 < 256) ? (w_in + (size_t)k0*UNITS) : (w_rec + (size_t)(k0-256)*UNITS);
    const float* W1 = (k1 < 256) ? (w_in + (size_t)k1*UNITS) : (w_rec + (size_t)(k1-256)*UNITS);
    float2 o;
    o.x = __uint_as_float(cvt_tf32(W0[n]));
    o.y = __uint_as_float(cvt_tf32(W1[n]));
    g_Bt[t] = o;
}

// ---------------- main fused kernel ----------------
__global__ __launch_bounds__(512, 1)
void jfc_main(const float* __restrict__ inputs,
              const float* __restrict__ prev_h,
              const float* __restrict__ prev_G,
              const float* __restrict__ prev_phase,
              const float* __restrict__ bias,
              float* __restrict__ out_h,
              float* __restrict__ out_G,
              float* __restrict__ out_phase)
{
    extern __shared__ __align__(16) char smem[];
    const uint32_t base = smaddr(smem);
    const uint32_t sA0 = base;
    const uint32_t sA1 = base + ABUF_BYTES;
    const uint32_t sB0 = base + 2*ABUF_BYTES;
    const uint32_t sB1 = sB0 + BBUF_BYTES;
    float4* stats = (float4*)(smem + STATS_OFF);

    const int tid  = threadIdx.x;
    const int lane = tid & 31, wid = tid >> 5;
    const int g  = lane >> 2, t4 = lane & 3;
    const int m0w = (wid >> 2) * 32;     // warp M origin
    const int n0w = (wid & 3) * 64;      // warp N origin
    const int rowBase = blockIdx.x * TILE_M;

    // A loader mapping: thread -> row m_l, k8-chunk c_l (owns full chunk: k=c*8..c*8+7)
    const int m_l = tid >> 2;            // 0..127
    const int c_l = tid & 3;             // 0..3

    float acc[2][8][4];
    #pragma unroll
    for (int a = 0; a < 2; a++)
        #pragma unroll
        for (int b = 0; b < 8; b++)
            #pragma unroll
            for (int c = 0; c < 4; c++) acc[a][b][c] = 0.0f;

    float4 av0, av1;

    // A store: interleave so (k, k+4) are adjacent -> LDS.64 yields {a_k, a_k+4}
    auto storeA = [&](uint32_t sdst){
        uint32_t ab = sdst + (m_l*ASTRIDE + c_l*8)*4;
        sts64(ab +  0, cvt_tf32(av0.x), cvt_tf32(av1.x));
        sts64(ab +  8, cvt_tf32(av0.y), cvt_tf32(av1.y));
        sts64(ab + 16, cvt_tf32(av0.z), cvt_tf32(av1.z));
        sts64(ab + 24, cvt_tf32(av0.w), cvt_tf32(av1.w));
    };

    // ---- prologue: stage 0 ----
    {
        const float* src = inputs + (size_t)(rowBase + m_l)*UNITS + c_l*8;
        av0 = *(const float4*)src;          // k = c*8 .. c*8+3
        av1 = *(const float4*)(src + 4);    // k = c*8+4 .. c*8+7
        const char* bsrc = (const char*)g_Bt;
        #pragma unroll
        for (int i = 0; i < 4; i++) cp16(sB0 + (tid + 512*i)*16, bsrc + (size_t)(tid + 512*i)*16);
        asm volatile("cp.async.commit_group;");
        storeA(sA0);
        asm volatile("cp.async.wait_group 0;");
        __syncthreads();
    }

    // ---- mainloop: 16 stages of BK=32, double-buffered ----
    for (int s = 0; s < NSTAGE; s++) {
        const int pp = s & 1;
        const uint32_t sAc = pp ? sA1 : sA0;
        const uint32_t sBc = pp ? sB1 : sB0;
        const uint32_t sAn = pp ? sA0 : sA1;
        const uint32_t sBn = pp ? sB0 : sB1;

        if (s + 1 < NSTAGE) {
            const int s1 = s + 1;
            const float* srcb = ((s1 < 8) ? inputs : prev_h)
                              + (size_t)(rowBase + m_l)*UNITS + (s1 & 7)*BK + c_l*8;
            av0 = *(const float4*)srcb;
            av1 = *(const float4*)(srcb + 4);
            const char* bsrc = (const char*)g_Bt + (size_t)s1 * BBUF_BYTES;
            #pragma unroll
            for (int i = 0; i < 4; i++) cp16(sBn + (tid + 512*i)*16, bsrc + (size_t)(tid + 512*i)*16);
            asm volatile("cp.async.commit_group;");
        }

        // compute 4 k8-steps on current buffers
        #pragma unroll
        for (int kc = 0; kc < 4; kc++) {
            uint2 bfr[8];
            const uint32_t bb = sBc + (kc*2048 + (n0w + g)*8 + t4*2)*4;
            #pragma unroll
            for (int nt = 0; nt < 8; nt++) bfr[nt] = lds64(bb + nt*256);

            uint2 arg[2], arg8[2];
            #pragma unroll
            for (int mt = 0; mt < 2; mt++) {
                uint32_t aa = sAc + ((m0w + mt*16 + g)*ASTRIDE + kc*8 + 2*t4)*4;
                arg[mt]  = lds64(aa);                    // {(g, t4), (g, t4+4)}
                arg8[mt] = lds64(aa + 8*ASTRIDE*4);      // {(g+8, t4), (g+8, t4+4)}
            }
            #pragma unroll
            for (int mt = 0; mt < 2; mt++)
                #pragma unroll
                for (int nt = 0; nt < 8; nt++)
                    mma_tf32(acc[mt][nt], arg[mt], arg8[mt], bfr[nt]);
        }

        if (s + 1 < NSTAGE) {
            storeA(sAn);
            asm volatile("cp.async.wait_group 0;");
        }
        __syncthreads();
    }

    // ---- epilogue phase 1: per-row stats (warp w owns rows w*8..w*8+7) ----
    const float inv_units = 1.0f / 256.0f;
    const float dphase = 0.2513274122871834f;   // 2*pi/25
    #pragma unroll
    for (int i = 0; i < 8; i++) {
        const int r = wid*8 + i;
        const size_t rowOff = (size_t)(rowBase + r) * UNITS;
        float sG = 0.f, sG2 = 0.f, sR = 0.f;
        #pragma unroll
        for (int j = 0; j < 8; j++) {
            int c = lane + 32*j;
            float raw = prev_h[rowOff + (c ^ 128)];
            float pg  = prev_G[rowOff + c];
            float gv  = 0.9f*pg + 0.1f*raw;
            out_G[rowOff + c] = gv;
            sG += gv; sG2 += gv*gv; sR += raw;
        }
        #pragma unroll
        for (int off = 16; off; off >>= 1) {
            sG  += __shfl_xor_sync(0xffffffffu, sG,  off);
            sG2 += __shfl_xor_sync(0xffffffffu, sG2, off);
            sR  += __shfl_xor_sync(0xffffffffu, sR,  off);
        }
        float mean = sG * inv_units;
        float var  = fmaxf(sG2 * inv_units - mean*mean, 0.0f);
        float invd = 1.0f / (sqrtf(var) + 1e-6f);
        float nphase = prev_phase[rowBase + r] + dphase;
        float cf = 0.5f * (sinf(nphase) + 0.05f * (sR * inv_units - 0.1f));
        if (lane == 0) {
            stats[r] = make_float4(mean, invd, cf, 0.0f);
            out_phase[rowBase + r] = nphase;
        }
    }
    __syncthreads();

    // ---- epilogue phase 2: finish pointwise from register accumulators ----
    #pragma unroll
    for (int mt = 0; mt < 2; mt++) {
        const int lm1 = m0w + mt*16 + g;
        const int lm2 = lm1 + 8;
        const float4 s1 = stats[lm1];
        const float4 s2 = stats[lm2];
        const size_t ro1 = (size_t)(rowBase + lm1) * UNITS;
        const size_t ro2 = (size_t)(rowBase + lm2) * UNITS;
        #pragma unroll
        for (int nt = 0; nt < 8; nt++) {
            const int cA = n0w + nt*8 + 2*t4;
            const float2 bs = *(const float2*)&bias[cA];
            #pragma unroll
            for (int half = 0; half < 2; half++) {
                const float4 st  = half ? s2  : s1;
                const size_t ro  = half ? ro2 : ro1;
                const float z0   = acc[mt][nt][half*2 + 0];
                const float z1   = acc[mt][nt][half*2 + 1];
                const float2 gg  = *(const float2*)&out_G[ro + cA];
                const float2 ph  = *(const float2*)&prev_h[ro + cA];
                float f0 = 1.0f + st.z * tanhf((gg.x - st.x) * st.y);
                float f1 = 1.0f + st.z * tanhf((gg.y - st.x) * st.y);
                float zz0 = (z0 + bs.x) * f0;
                float zz1 = (z1 + bs.y) * f1;
                float e0 = (zz0 > 0.0f) ? zz0 : expm1f(zz0);
                float e1 = (zz1 > 0.0f) ? zz1 : expm1f(zz1);
                float h0 = 0.9f*ph.x + 0.1f*e0;
                float h1 = 0.9f*ph.y + 0.1f*e1;
                h0 = fminf(fmaxf(h0, -20.0f), 20.0f);
                h1 = fminf(fmaxf(h1, -20.0f), 20.0f);
                float2 o = make_float2(h0, h1);
                *(float2*)&out_h[ro + cA] = o;
            }
        }
    }
}

extern "C" void kernel_launch(void* const* d_in, const int* in_sizes, int n_in,
                              void* d_out, int out_size) {
    const float* inputs     = (const float*)d_in[0];
    const float* prev_h     = (const float*)d_in[1];
    const float* prev_G     = (const float*)d_in[2];
    const float* prev_phase = (const float*)d_in[3];
    const float* w_in       = (const float*)d_in[4];
    const float* w_rec      = (const float*)d_in[5];
    const float* bias       = (const float*)d_in[6];

    float* out   = (float*)d_out;
    float* out_h = out;
    float* out_G = out + (size_t)BATCH * UNITS;
    float* out_p = out + 2 * (size_t)BATCH * UNITS;

    cudaFuncSetAttribute(jfc_main, cudaFuncAttributeMaxDynamicSharedMemorySize, SMEM_BYTES);

    prep_B<<<256, 256>>>(w_in, w_rec);
    jfc_main<<<NBLK, 512, SMEM_BYTES>>>(inputs, prev_h, prev_G, prev_phase, bias,
                                        out_h, out_G, out_p);
}

// round 5
// speedup vs baseline: 2.8128x; 1.2836x over previous
#include <cuda_runtime.h>
#include <math.h>
#include <stdint.h>

#define BATCH 65536
#define UNITS 256
#define KTOT  512
#define TILE_M 64
#define BK 32
#define NSTAGE 16
#define NBLK (BATCH/TILE_M)        // 1024

#define ASTRIDE 36                               // words per A row (32 + 4 pad)
#define ABUF_BYTES (TILE_M*ASTRIDE*4)            // 9216
#define BBUF_BYTES (BK*UNITS*4)                  // 32768
#define STATS_OFF  (2*ABUF_BYTES + 2*BBUF_BYTES) // 83968
#define SMEM_BYTES (STATS_OFF + TILE_M*16)       // 84992
#define GSTRIDE 260                              // padded row stride for G smem cache

// Pre-baked weights: [q=0..63][n=0..255][p=0..3] float2 pairs,
// pair = { tf32(W[8q+p][n]), tf32(W[8q+p+4][n]) }   (mma b0/b1 = k=t4, k=t4+4)
__device__ __align__(16) float2 g_Bt[64*256*4];

// ---------------- helpers ----------------
__device__ __forceinline__ uint32_t smaddr(const void* p){
    uint32_t a;
    asm("{ .reg .u64 t; cvta.to.shared.u64 t, %1; cvt.u32.u64 %0, t; }" : "=r"(a) : "l"(p));
    return a;
}
__device__ __forceinline__ uint32_t cvt_tf32(float v){
    uint32_t t; asm("cvt.rna.tf32.f32 %0, %1;" : "=r"(t) : "f"(v)); return t;
}
__device__ __forceinline__ void cp16(uint32_t d, const void* s){
    asm volatile("cp.async.cg.shared.global [%0], [%1], 16;" :: "r"(d), "l"(s));
}
__device__ __forceinline__ uint2 lds64(uint32_t a){
    uint2 v;
    asm volatile("ld.shared.v2.b32 {%0,%1}, [%2];" : "=r"(v.x), "=r"(v.y) : "r"(a));
    return v;
}
__device__ __forceinline__ void sts64(uint32_t a, uint32_t v0, uint32_t v1){
    asm volatile("st.shared.v2.b32 [%0], {%1,%2};" :: "r"(a), "r"(v0), "r"(v1));
}
// a-regs in spec order a0=(g,t4) a1=(g+8,t4) a2=(g,t4+4) a3=(g+8,t4+4)
__device__ __forceinline__ void mma_tf32(float* d, uint2 rg, uint2 rg8, uint2 b){
    asm("mma.sync.aligned.m16n8k8.row.col.f32.tf32.tf32.f32 "
        "{%0,%1,%2,%3}, {%4,%5,%6,%7}, {%8,%9}, {%0,%1,%2,%3};"
        : "+f"(d[0]), "+f"(d[1]), "+f"(d[2]), "+f"(d[3])
        : "r"(rg.x), "r"(rg8.x), "r"(rg.y), "r"(rg8.y), "r"(b.x), "r"(b.y));
}

// ---------------- prep: tf32-convert + (k, k+4)-pair weights ----------------
__global__ void prep_B(const float* __restrict__ w_in, const float* __restrict__ w_rec){
    int t = blockIdx.x * 256 + threadIdx.x;        // 0..65535
    int p = t & 3, n = (t >> 2) & 255, q = t >> 10;
    int k0 = 8*q + p;
    int k1 = k0 + 4;
    const float* W0 = (k0 < 256) ? (w_in + (size_t)k0*UNITS) : (w_rec + (size_t)(k0-256)*UNITS);
    const float* W1 = (k1 < 256) ? (w_in + (size_t)k1*UNITS) : (w_rec + (size_t)(k1-256)*UNITS);
    float2 o;
    o.x = __uint_as_float(cvt_tf32(W0[n]));
    o.y = __uint_as_float(cvt_tf32(W1[n]));
    g_Bt[t] = o;
}

// ---------------- main fused kernel: 256 thr, 2 CTAs/SM ----------------
__global__ __launch_bounds__(256, 2)
void jfc_main(const float* __restrict__ inputs,
              const float* __restrict__ prev_h,
              const float* __restrict__ prev_G,
              const float* __restrict__ prev_phase,
              const float* __restrict__ bias,
              float* __restrict__ out_h,
              float* __restrict__ out_G,
              float* __restrict__ out_phase)
{
    extern __shared__ __align__(16) char smem[];
    const uint32_t base = smaddr(smem);
    const uint32_t sA0 = base;
    const uint32_t sA1 = base + ABUF_BYTES;
    const uint32_t sB0 = base + 2*ABUF_BYTES;
    const uint32_t sB1 = sB0 + BBUF_BYTES;
    float4* stats = (float4*)(smem + STATS_OFF);
    float*  Gbuf  = (float*)smem;                 // overlays A/B after mainloop

    const int tid  = threadIdx.x;
    const int lane = tid & 31, wid = tid >> 5;    // wid 0..7
    const int g  = lane >> 2, t4 = lane & 3;
    const int m0w = (wid >> 2) * 32;              // warp M origin {0,32}
    const int n0w = (wid & 3) * 64;               // warp N origin {0,64,128,192}
    const int rowBase = blockIdx.x * TILE_M;

    // A loader mapping: thread -> row m_l (0..63), k8-chunk c_l (0..3)
    const int m_l = tid >> 2;
    const int c_l = tid & 3;

    float acc[2][8][4];
    #pragma unroll
    for (int a = 0; a < 2; a++)
        #pragma unroll
        for (int b = 0; b < 8; b++)
            #pragma unroll
            for (int c = 0; c < 4; c++) acc[a][b][c] = 0.0f;

    float4 av0, av1;

    // A store: interleave so (k, k+4) adjacent -> LDS.64 yields {a_k, a_k+4}
    auto storeA = [&](uint32_t sdst){
        uint32_t ab = sdst + (m_l*ASTRIDE + c_l*8)*4;
        sts64(ab +  0, cvt_tf32(av0.x), cvt_tf32(av1.x));
        sts64(ab +  8, cvt_tf32(av0.y), cvt_tf32(av1.y));
        sts64(ab + 16, cvt_tf32(av0.z), cvt_tf32(av1.z));
        sts64(ab + 24, cvt_tf32(av0.w), cvt_tf32(av1.w));
    };

    // ---- prologue: stage 0 ----
    {
        const float* src = inputs + (size_t)(rowBase + m_l)*UNITS + c_l*8;
        av0 = *(const float4*)src;
        av1 = *(const float4*)(src + 4);
        const char* bsrc = (const char*)g_Bt;
        #pragma unroll
        for (int i = 0; i < 8; i++) cp16(sB0 + (tid + 256*i)*16, bsrc + (size_t)(tid + 256*i)*16);
        asm volatile("cp.async.commit_group;");
        storeA(sA0);
        asm volatile("cp.async.wait_group 0;");
        __syncthreads();
    }

    // ---- mainloop: 16 stages of BK=32, double-buffered ----
    for (int s = 0; s < NSTAGE; s++) {
        const int pp = s & 1;
        const uint32_t sAc = pp ? sA1 : sA0;
        const uint32_t sBc = pp ? sB1 : sB0;
        const uint32_t sAn = pp ? sA0 : sA1;
        const uint32_t sBn = pp ? sB0 : sB1;

        if (s + 1 < NSTAGE) {
            const int s1 = s + 1;
            const float* srcb = ((s1 < 8) ? inputs : prev_h)
                              + (size_t)(rowBase + m_l)*UNITS + (s1 & 7)*BK + c_l*8;
            av0 = *(const float4*)srcb;
            av1 = *(const float4*)(srcb + 4);
            const char* bsrc = (const char*)g_Bt + (size_t)s1 * BBUF_BYTES;
            #pragma unroll
            for (int i = 0; i < 8; i++) cp16(sBn + (tid + 256*i)*16, bsrc + (size_t)(tid + 256*i)*16);
            asm volatile("cp.async.commit_group;");
        }

        // compute 4 k8-steps on current buffers
        #pragma unroll
        for (int kc = 0; kc < 4; kc++) {
            uint2 bfr[8];
            const uint32_t bb = sBc + (kc*2048 + (n0w + g)*8 + t4*2)*4;
            #pragma unroll
            for (int nt = 0; nt < 8; nt++) bfr[nt] = lds64(bb + nt*256);

            uint2 arg[2], arg8[2];
            #pragma unroll
            for (int mt = 0; mt < 2; mt++) {
                uint32_t aa = sAc + ((m0w + mt*16 + g)*ASTRIDE + kc*8 + 2*t4)*4;
                arg[mt]  = lds64(aa);                    // {(g, t4), (g, t4+4)}
                arg8[mt] = lds64(aa + 8*ASTRIDE*4);      // {(g+8, t4), (g+8, t4+4)}
            }
            #pragma unroll
            for (int mt = 0; mt < 2; mt++)
                #pragma unroll
                for (int nt = 0; nt < 8; nt++)
                    mma_tf32(acc[mt][nt], arg[mt], arg8[mt], bfr[nt]);
        }

        if (s + 1 < NSTAGE) {
            storeA(sAn);
            asm volatile("cp.async.wait_group 0;");
        }
        __syncthreads();
    }

    // ---- epilogue phase 1: per-row stats (warp w owns rows w*8..w*8+7) ----
    const float inv_units = 1.0f / 256.0f;
    const float dphase = 0.2513274122871834f;   // 2*pi/25
    #pragma unroll
    for (int i = 0; i < 8; i++) {
        const int r = wid*8 + i;
        const size_t rowOff = (size_t)(rowBase + r) * UNITS;
        float sG = 0.f, sG2 = 0.f, sR = 0.f;
        #pragma unroll
        for (int j = 0; j < 8; j++) {
            int c = lane + 32*j;
            float raw = prev_h[rowOff + (c ^ 128)];
            float pg  = prev_G[rowOff + c];
            float gv  = 0.9f*pg + 0.1f*raw;
            out_G[rowOff + c] = gv;
            Gbuf[r*GSTRIDE + c] = gv;
            sG += gv; sG2 += gv*gv; sR += raw;
        }
        #pragma unroll
        for (int off = 16; off; off >>= 1) {
            sG  += __shfl_xor_sync(0xffffffffu, sG,  off);
            sG2 += __shfl_xor_sync(0xffffffffu, sG2, off);
            sR  += __shfl_xor_sync(0xffffffffu, sR,  off);
        }
        float mean = sG * inv_units;
        float var  = fmaxf(sG2 * inv_units - mean*mean, 0.0f);
        float invd = 1.0f / (sqrtf(var) + 1e-6f);
        float nphase = prev_phase[rowBase + r] + dphase;
        float cf = 0.5f * (sinf(nphase) + 0.05f * (sR * inv_units - 0.1f));
        if (lane == 0) {
            stats[r] = make_float4(mean, invd, cf, 0.0f);
            out_phase[rowBase + r] = nphase;
        }
    }
    __syncthreads();

    // ---- epilogue phase 2: finish pointwise from register accumulators ----
    #pragma unroll
    for (int mt = 0; mt < 2; mt++) {
        const int lm1 = m0w + mt*16 + g;
        const int lm2 = lm1 + 8;
        const float4 s1 = stats[lm1];
        const float4 s2 = stats[lm2];
        const size_t ro1 = (size_t)(rowBase + lm1) * UNITS;
        const size_t ro2 = (size_t)(rowBase + lm2) * UNITS;
        #pragma unroll
        for (int nt = 0; nt < 8; nt++) {
            const int cA = n0w + nt*8 + 2*t4;
            const float2 bs = *(const float2*)&bias[cA];
            #pragma unroll
            for (int half = 0; half < 2; half++) {
                const float4 st  = half ? s2  : s1;
                const size_t ro  = half ? ro2 : ro1;
                const int    lm  = half ? lm2 : lm1;
                const float z0   = acc[mt][nt][half*2 + 0];
                const float z1   = acc[mt][nt][half*2 + 1];
                const float2 gg  = *(const float2*)&Gbuf[lm*GSTRIDE + cA];
                const float2 ph  = *(const float2*)&prev_h[ro + cA];
                float f0 = 1.0f + st.z * tanhf((gg.x - st.x) * st.y);
                float f1 = 1.0f + st.z * tanhf((gg.y - st.x) * st.y);
                float zz0 = (z0 + bs.x) * f0;
                float zz1 = (z1 + bs.y) * f1;
                float e0 = (zz0 > 0.0f) ? zz0 : expm1f(zz0);
                float e1 = (zz1 > 0.0f) ? zz1 : expm1f(zz1);
                float h0 = 0.9f*ph.x + 0.1f*e0;
                float h1 = 0.9f*ph.y + 0.1f*e1;
                h0 = fminf(fmaxf(h0, -20.0f), 20.0f);
                h1 = fminf(fmaxf(h1, -20.0f), 20.0f);
                float2 o = make_float2(h0, h1);
                *(float2*)&out_h[ro + cA] = o;
            }
        }
    }
}

extern "C" void kernel_launch(void* const* d_in, const int* in_sizes, int n_in,
                              void* d_out, int out_size) {
    const float* inputs     = (const float*)d_in[0];
    const float* prev_h     = (const float*)d_in[1];
    const float* prev_G     = (const float*)d_in[2];
    const float* prev_phase = (const float*)d_in[3];
    const float* w_in       = (const float*)d_in[4];
    const float* w_rec      = (const float*)d_in[5];
    const float* bias       = (const float*)d_in[6];

    float* out   = (float*)d_out;
    float* out_h = out;
    float* out_G = out + (size_t)BATCH * UNITS;
    float* out_p = out + 2 * (size_t)BATCH * UNITS;

    cudaFuncSetAttribute(jfc_main, cudaFuncAttributeMaxDynamicSharedMemorySize, SMEM_BYTES);

    prep_B<<<256, 256>>>(w_in, w_rec);
    jfc_main<<<NBLK, 256, SMEM_BYTES>>>(inputs, prev_h, prev_G, prev_phase, bias,
                                        out_h, out_G, out_p);
}